// round 14
// baseline (speedup 1.0000x reference)
#include <cuda_runtime.h>
#include <cuda_fp16.h>
#include <cstdint>

// Problem constants (fixed by the dataset)
#define N0 320000
#define N1 80000
#define N2 16000
#define E1 800000
#define E2 160000
#define INC 128
#define F1  256    // H1*HID = 4*64
#define OUTC 48

#define NB1 79     // ceil((N1+1)/1024)
#define NB2 16     // ceil((N2+1)/1024)
#define NGEMM1 (N0 / 128)          // 2500
#define NCNT 235                   // ceil((E1/4 + E2/4) / 1024)
#define WTOT (2 * F1 * INC + 2 * OUTC * F1)   // 90112 weight-transpose elements

// ---------------- scratch (static device globals; no runtime allocation) ----
__device__ __half g_xl1h[(size_t)N0 * F1];
__device__ __half g_xr1h[(size_t)N1 * F1];
__device__ __half g_hh [(size_t)N1 * F1];
__device__ __half g_w1l[(size_t)F1 * INC];
__device__ __half g_w1r[(size_t)F1 * INC];
__device__ __half g_w2l[(size_t)OUTC * F1];
__device__ __half g_w2r[(size_t)OUTC * F1];
__device__ float  g_xl2[(size_t)N1 * OUTC];
__device__ float  g_xr2[(size_t)N2 * OUTC];

__device__ int g_deg1[N1 + 1];
__device__ int g_off1[N1 + 1];
__device__ int g_cur1[N1];
__device__ int g_csr1[E1];
__device__ int g_deg2[N2 + 1];
__device__ int g_off2[N2 + 1];
__device__ int g_cur2[N2];
__device__ int g_csr2[E2];
__device__ int g_bsums[128];
__device__ int g_flags[128];

// ---------------- helpers ----------------------------------------------------
__device__ __forceinline__ uint32_t smem_to_u32(const void* p) {
    uint32_t a;
    asm("{ .reg .u64 t; cvta.to.shared.u64 t, %1; cvt.u32.u64 %0, t; }" : "=r"(a) : "l"(p));
    return a;
}
__device__ __forceinline__ void ldm_x4(uint32_t* r, uint32_t addr) {
    asm volatile("ldmatrix.sync.aligned.m8n8.x4.shared.b16 {%0,%1,%2,%3}, [%4];"
                 : "=r"(r[0]), "=r"(r[1]), "=r"(r[2]), "=r"(r[3]) : "r"(addr));
}
__device__ __forceinline__ void ldm_x2(uint32_t* r, uint32_t addr) {
    asm volatile("ldmatrix.sync.aligned.m8n8.x2.shared.b16 {%0,%1}, [%2];"
                 : "=r"(r[0]), "=r"(r[1]) : "r"(addr));
}
__device__ __forceinline__ void mma16816(float* c, const uint32_t* a, const uint32_t* b) {
    asm volatile("mma.sync.aligned.m16n8k16.row.col.f32.f16.f16.f32 "
                 "{%0,%1,%2,%3}, {%4,%5,%6,%7}, {%8,%9}, {%0,%1,%2,%3};"
                 : "+f"(c[0]), "+f"(c[1]), "+f"(c[2]), "+f"(c[3])
                 : "r"(a[0]), "r"(a[1]), "r"(a[2]), "r"(a[3]), "r"(b[0]), "r"(b[1]));
}

// ---------------- prep: weight transposes + zero deg/flags (one launch) -----
// GRID MUST COVER max(WTOT, N1+1) = 90112 elements (R12 bug: was sized N1+1,
// leaving 81% of w2r zero -> corrupted xr2 attention logits, rel_err 8.6e-4).
__global__ void prep_k(const float* __restrict__ Wl1, const float* __restrict__ Wr1,
                       const float* __restrict__ Wl2, const float* __restrict__ Wr2,
                       __half* __restrict__ w1l, __half* __restrict__ w1r,
                       __half* __restrict__ w2l, __half* __restrict__ w2r,
                       int* __restrict__ deg1, int* __restrict__ deg2,
                       int* __restrict__ flags) {
    const int S1 = F1 * INC;     // 32768
    const int S2 = OUTC * F1;    // 12288
    int i = blockIdx.x * blockDim.x + threadIdx.x;
    if (i < S1) {
        int n = i / INC, k = i % INC;
        w1l[i] = __float2half(Wl1[(size_t)k * F1 + n]);
    } else if (i < 2 * S1) {
        int j = i - S1, n = j / INC, k = j % INC;
        w1r[j] = __float2half(Wr1[(size_t)k * F1 + n]);
    } else if (i < 2 * S1 + S2) {
        int j = i - 2 * S1, n = j / F1, k = j % F1;
        w2l[j] = __float2half(Wl2[(size_t)k * OUTC + n]);
    } else if (i < 2 * S1 + 2 * S2) {
        int j = i - 2 * S1 - S2, n = j / F1, k = j % F1;
        w2r[j] = __float2half(Wr2[(size_t)k * OUTC + n]);
    }
    if (i < N1 + 1) deg1[i] = 0;
    if (i < N2 + 1) deg2[i] = 0;
    if (i < 128) flags[i] = 0;
}

// ---------------- fused layer-1 GEMM + edge counting (one launch) -----------
#define ASTRIDE 136
__global__ __launch_bounds__(256) void gemm1_fused_k(
    const float* __restrict__ x,
    const __half* __restrict__ w1l, const __half* __restrict__ w1r,
    const float* __restrict__ bl1, const float* __restrict__ br1,
    __half* __restrict__ xl, __half* __restrict__ xr, int nr_blocks,
    const int* __restrict__ dst1, const int* __restrict__ dst2,
    int* __restrict__ deg1, int* __restrict__ deg2)
{
    int tid = threadIdx.x;
    if (blockIdx.y >= NGEMM1) {
        int cb = blockIdx.y - NGEMM1;
        #pragma unroll
        for (int u = 0; u < 4; u++) {
            int i = cb * 1024 + u * 256 + tid;
            if (i < E1 / 4) {
                int4 d = ((const int4*)dst1)[i];
                atomicAdd(&deg1[d.x], 1); atomicAdd(&deg1[d.y], 1);
                atomicAdd(&deg1[d.z], 1); atomicAdd(&deg1[d.w], 1);
            } else if (i < E1 / 4 + E2 / 4) {
                int4 d = ((const int4*)dst2)[i - E1 / 4];
                atomicAdd(&deg2[d.x], 1); atomicAdd(&deg2[d.y], 1);
                atomicAdd(&deg2[d.z], 1); atomicAdd(&deg2[d.w], 1);
            }
        }
        return;
    }

    extern __shared__ __half sm[];
    __half* As = sm;
    __half* Bs = sm + 128 * ASTRIDE;

    int lane = tid & 31, wid = tid >> 5;
    int wm = wid >> 1, wn = wid & 1;
    size_t m0 = (size_t)blockIdx.y * 128;

    uint32_t asb = smem_to_u32(As), bsb = smem_to_u32(Bs);

    for (int i = tid; i < 2048; i += 256) {
        int r = i >> 4, c8 = (i & 15) * 8;
        const float* p = &x[(m0 + r) * INC + c8];
        float4 v0 = *(const float4*)p;
        float4 v1 = *(const float4*)(p + 4);
        __half2 h[4] = {__floats2half2_rn(v0.x, v0.y), __floats2half2_rn(v0.z, v0.w),
                        __floats2half2_rn(v1.x, v1.y), __floats2half2_rn(v1.z, v1.w)};
        *(uint4*)&As[r * ASTRIDE + c8] = *(uint4*)h;
    }

    int npass = (blockIdx.y < (unsigned)nr_blocks) ? 4 : 2;
    for (int pass = 0; pass < npass; pass++) {
        const __half* B = (pass < 2) ? w1l : w1r;
        const float* bias = (pass < 2) ? bl1 : br1;
        __half* dst = (pass < 2) ? xl : xr;
        int nb = (pass & 1) * 128;

        __syncthreads();
        for (int i = tid; i < 2048; i += 256) {
            int r = i >> 4, c8 = (i & 15) * 8;
            *(uint4*)&Bs[r * ASTRIDE + c8] = *(const uint4*)&B[(size_t)(nb + r) * INC + c8];
        }
        __syncthreads();

        float c[2][8][4] = {};
        #pragma unroll
        for (int kk = 0; kk < 8; kk++) {
            uint32_t af[2][4], bf[8][2];
            #pragma unroll
            for (int mt = 0; mt < 2; mt++) {
                int row = wm * 32 + mt * 16 + (lane & 7) + ((lane >> 3) & 1) * 8;
                int col = kk * 16 + (lane >> 4) * 8;
                ldm_x4(af[mt], asb + (uint32_t)(row * ASTRIDE + col) * 2);
            }
            #pragma unroll
            for (int nt = 0; nt < 8; nt++) {
                int row = wn * 64 + nt * 8 + (lane & 7);
                int col = kk * 16 + ((lane >> 3) & 1) * 8;
                ldm_x2(bf[nt], bsb + (uint32_t)(row * ASTRIDE + col) * 2);
            }
            #pragma unroll
            for (int mt = 0; mt < 2; mt++)
                #pragma unroll
                for (int nt = 0; nt < 8; nt++)
                    mma16816(c[mt][nt], af[mt], bf[nt]);
        }

        #pragma unroll
        for (int mt = 0; mt < 2; mt++) {
            size_t r0 = m0 + wm * 32 + mt * 16 + (lane >> 2);
            #pragma unroll
            for (int nt = 0; nt < 8; nt++) {
                int col = nb + wn * 64 + nt * 8 + (lane & 3) * 2;
                float bx = bias[col], by = bias[col + 1];
                *(__half2*)&dst[r0 * F1 + col] =
                    __floats2half2_rn(c[mt][nt][0] + bx, c[mt][nt][1] + by);
                *(__half2*)&dst[(r0 + 8) * F1 + col] =
                    __floats2half2_rn(c[mt][nt][2] + bx, c[mt][nt][3] + by);
            }
        }
    }
}

// ---------------- one-launch two-level scan with warp-parallel lookback -----
__global__ __launch_bounds__(1024) void scan_lb_k(
    const int* __restrict__ deg1, int* __restrict__ off1, int* __restrict__ cur1,
    const int* __restrict__ deg2, int* __restrict__ off2, int* __restrict__ cur2,
    int* __restrict__ bsums, int* __restrict__ flags)
{
    __shared__ int s[1024];
    __shared__ int sprefix;
    int b = blockIdx.x;
    const int* in; int* out; int* cur; int n; int nnode; int seg0;
    if (b < NB1) { in = deg1; out = off1; cur = cur1; n = N1 + 1; nnode = N1; seg0 = 0; }
    else         { in = deg2; out = off2; cur = cur2; n = N2 + 1; nnode = N2; seg0 = NB1; }
    int bi = b - seg0;
    int tid = threadIdx.x;
    int i = bi * 1024 + tid;
    int v = (i < n) ? in[i] : 0;
    s[tid] = v;
    __syncthreads();
    for (int d = 1; d < 1024; d <<= 1) {
        int t = (tid >= d) ? s[tid - d] : 0;
        __syncthreads();
        s[tid] += t;
        __syncthreads();
    }
    if (tid == 0) {
        bsums[b] = s[1023];
        __threadfence();
        atomicExch(&flags[b], 1);
    }
    if (tid < 32) {
        int p = 0;
        for (int j = seg0 + tid; j < b; j += 32) {
            while (atomicAdd(&flags[j], 0) == 0) {}
            p += atomicAdd(&bsums[j], 0);
        }
        #pragma unroll
        for (int o = 16; o; o >>= 1) p += __shfl_xor_sync(0xffffffffu, p, o);
        if (tid == 0) sprefix = p;
    }
    __syncthreads();
    int pre = sprefix;
    if (i < n) {
        int e = pre + s[tid] - v;
        out[i] = e;
        if (i < nnode) cur[i] = e;
    }
}

// vectorized scatter: 4 edges per thread (int4 loads of src/dst)
__global__ void scatter_both_k(const int* __restrict__ src1, const int* __restrict__ dst1,
                               int* __restrict__ cur1, int* __restrict__ csr1,
                               const int* __restrict__ src2, const int* __restrict__ dst2,
                               int* __restrict__ cur2, int* __restrict__ csr2) {
    int i = blockIdx.x * blockDim.x + threadIdx.x;
    if (i < E1 / 4) {
        int4 d = ((const int4*)dst1)[i];
        int4 sv = ((const int4*)src1)[i];
        csr1[atomicAdd(&cur1[d.x], 1)] = sv.x;
        csr1[atomicAdd(&cur1[d.y], 1)] = sv.y;
        csr1[atomicAdd(&cur1[d.z], 1)] = sv.z;
        csr1[atomicAdd(&cur1[d.w], 1)] = sv.w;
    } else if (i < E1 / 4 + E2 / 4) {
        int j = i - E1 / 4;
        int4 d = ((const int4*)dst2)[j];
        int4 sv = ((const int4*)src2)[j];
        csr2[atomicAdd(&cur2[d.x], 1)] = sv.x;
        csr2[atomicAdd(&cur2[d.y], 1)] = sv.y;
        csr2[atomicAdd(&cur2[d.z], 1)] = sv.z;
        csr2[atomicAdd(&cur2[d.w], 1)] = sv.w;
    }
}

// ---------------- merged layer-2 GEMM ----------------------------------------
__global__ __launch_bounds__(256) void hmma_gemm2_k(
    const __half* __restrict__ A,
    const __half* __restrict__ BtL, const __half* __restrict__ BtR,
    const float* __restrict__ biasL, const float* __restrict__ biasR,
    float* __restrict__ CL, float* __restrict__ CR, int split)
{
    constexpr int BN = 48, WN = 24, NT = 3, K_DIM = F1, N_OUT = OUTC;
    __shared__ __half As[128][40];
    __shared__ __half Bs[BN][40];

    int tid = threadIdx.x, lane = tid & 31, wid = tid >> 5;
    int wm = wid >> 1, wn = wid & 1;

    const __half* Bt; const float* bias; float* C; size_t m0;
    if ((int)blockIdx.y < split) { Bt = BtL; bias = biasL; C = CL; m0 = (size_t)blockIdx.y * 128; }
    else                          { Bt = BtR; bias = biasR; C = CR; m0 = (size_t)(blockIdx.y - split) * 128; }

    uint32_t asb = smem_to_u32(As), bsb = smem_to_u32(Bs);
    float c[2][NT][4] = {};

    for (int k0 = 0; k0 < K_DIM; k0 += 32) {
        #pragma unroll
        for (int i = tid; i < 512; i += 256) {
            int r = i >> 2, cv = i & 3;
            *(uint4*)&As[r][cv * 8] = *(const uint4*)&A[(m0 + r) * K_DIM + k0 + cv * 8];
        }
        #pragma unroll
        for (int i = tid; i < BN * 4; i += 256) {
            int r = i >> 2, cv = i & 3;
            *(uint4*)&Bs[r][cv * 8] = *(const uint4*)&Bt[(size_t)r * K_DIM + k0 + cv * 8];
        }
        __syncthreads();

        #pragma unroll
        for (int kk = 0; kk < 2; kk++) {
            uint32_t af[2][4], bf[NT][2];
            #pragma unroll
            for (int mt = 0; mt < 2; mt++) {
                int row = wm * 32 + mt * 16 + (lane & 7) + ((lane >> 3) & 1) * 8;
                int col = kk * 16 + (lane >> 4) * 8;
                ldm_x4(af[mt], asb + (uint32_t)(row * 40 + col) * 2);
            }
            #pragma unroll
            for (int nt = 0; nt < NT; nt++) {
                int row = wn * WN + nt * 8 + (lane & 7);
                int col = kk * 16 + ((lane >> 3) & 1) * 8;
                ldm_x2(bf[nt], bsb + (uint32_t)(row * 40 + col) * 2);
            }
            #pragma unroll
            for (int mt = 0; mt < 2; mt++)
                #pragma unroll
                for (int nt = 0; nt < NT; nt++)
                    mma16816(c[mt][nt], af[mt], bf[nt]);
        }
        __syncthreads();
    }

    #pragma unroll
    for (int mt = 0; mt < 2; mt++) {
        size_t r0 = m0 + wm * 32 + mt * 16 + (lane >> 2);
        #pragma unroll
        for (int nt = 0; nt < NT; nt++) {
            int col = wn * WN + nt * 8 + (lane & 3) * 2;
            float bx = bias[col], by = bias[col + 1];
            float2 o0 = {c[mt][nt][0] + bx, c[mt][nt][1] + by};
            float2 o1 = {c[mt][nt][2] + bx, c[mt][nt][3] + by};
            *(float2*)&C[r0 * N_OUT + col] = o0;
            *(float2*)&C[(r0 + 8) * N_OUT + col] = o1;
        }
    }
}

__device__ __forceinline__ float leaky(float v) { return v > 0.f ? v : 0.2f * v; }

__device__ __forceinline__ float4 ldrow_h4(const __half* p) {
    uint2 u = *(const uint2*)p;
    __half2 h01 = *(__half2*)&u.x;
    __half2 h23 = *(__half2*)&u.y;
    float2 f01 = __half22float2(h01);
    float2 f23 = __half22float2(h23);
    return make_float4(f01.x, f01.y, f23.x, f23.y);
}

// ---------------- layer-1 aggregation ----------------------------------------
__global__ __launch_bounds__(64) void agg1_k(
    const __half* __restrict__ xl, const __half* __restrict__ xr,
    const int* __restrict__ csr, const int* __restrict__ off,
    const float* __restrict__ att, const float* __restrict__ bias,
    __half* __restrict__ out)
{
    int d = blockIdx.x;
    int t = threadIdx.x;
    int base = t * 4;
    float4 attv = *(const float4*)(att + base);
    float4 xrv  = ldrow_h4(xr + (size_t)d * F1 + base);

    float m = -3e38f, l = 0.f;
    float4 acc = {0.f, 0.f, 0.f, 0.f};

    int k0 = off[d], k1 = off[d + 1];
    int k = k0;
    for (; k + 4 <= k1; k += 4) {
        int s0 = csr[k], s1 = csr[k + 1], s2 = csr[k + 2], s3 = csr[k + 3];
        float4 xa = ldrow_h4(xl + (size_t)s0 * F1 + base);
        float4 xb = ldrow_h4(xl + (size_t)s1 * F1 + base);
        float4 xc = ldrow_h4(xl + (size_t)s2 * F1 + base);
        float4 xd = ldrow_h4(xl + (size_t)s3 * F1 + base);
        float pa = leaky(xa.x + xrv.x) * attv.x + leaky(xa.y + xrv.y) * attv.y
                 + leaky(xa.z + xrv.z) * attv.z + leaky(xa.w + xrv.w) * attv.w;
        float pb = leaky(xb.x + xrv.x) * attv.x + leaky(xb.y + xrv.y) * attv.y
                 + leaky(xb.z + xrv.z) * attv.z + leaky(xb.w + xrv.w) * attv.w;
        float pc = leaky(xc.x + xrv.x) * attv.x + leaky(xc.y + xrv.y) * attv.y
                 + leaky(xc.z + xrv.z) * attv.z + leaky(xc.w + xrv.w) * attv.w;
        float pd = leaky(xd.x + xrv.x) * attv.x + leaky(xd.y + xrv.y) * attv.y
                 + leaky(xd.z + xrv.z) * attv.z + leaky(xd.w + xrv.w) * attv.w;
        #pragma unroll
        for (int o = 8; o; o >>= 1) {
            pa += __shfl_xor_sync(0xffffffffu, pa, o);
            pb += __shfl_xor_sync(0xffffffffu, pb, o);
            pc += __shfl_xor_sync(0xffffffffu, pc, o);
            pd += __shfl_xor_sync(0xffffffffu, pd, o);
        }
        float mn = fmaxf(fmaxf(m, fmaxf(pa, pb)), fmaxf(pc, pd));
        float sc = __expf(m - mn);
        float ea = __expf(pa - mn);
        float eb = __expf(pb - mn);
        float ec = __expf(pc - mn);
        float ed = __expf(pd - mn);
        l = l * sc + ea + eb + ec + ed;
        acc.x = acc.x * sc + ea * xa.x + eb * xb.x + ec * xc.x + ed * xd.x;
        acc.y = acc.y * sc + ea * xa.y + eb * xb.y + ec * xc.y + ed * xd.y;
        acc.z = acc.z * sc + ea * xa.z + eb * xb.z + ec * xc.z + ed * xd.z;
        acc.w = acc.w * sc + ea * xa.w + eb * xb.w + ec * xc.w + ed * xd.w;
        m = mn;
    }
    for (; k < k1; k++) {
        int s = csr[k];
        float4 xv = ldrow_h4(xl + (size_t)s * F1 + base);
        float p = leaky(xv.x + xrv.x) * attv.x + leaky(xv.y + xrv.y) * attv.y
                + leaky(xv.z + xrv.z) * attv.z + leaky(xv.w + xrv.w) * attv.w;
        #pragma unroll
        for (int o = 8; o; o >>= 1) p += __shfl_xor_sync(0xffffffffu, p, o);
        float mn = fmaxf(m, p);
        float sc = __expf(m - mn);
        float pe = __expf(p - mn);
        l = l * sc + pe;
        acc.x = acc.x * sc + pe * xv.x;
        acc.y = acc.y * sc + pe * xv.y;
        acc.z = acc.z * sc + pe * xv.z;
        acc.w = acc.w * sc + pe * xv.w;
        m = mn;
    }
    float inv = 1.f / (l + 1e-16f);
    float4 bv = *(const float4*)(bias + base);
    float ox = fmaxf(acc.x * inv + bv.x, 0.f);
    float oy = fmaxf(acc.y * inv + bv.y, 0.f);
    float oz = fmaxf(acc.z * inv + bv.z, 0.f);
    float ow = fmaxf(acc.w * inv + bv.w, 0.f);
    __half2* hp = (__half2*)(out + (size_t)d * F1 + base);
    hp[0] = __floats2half2_rn(ox, oy);
    hp[1] = __floats2half2_rn(oz, ow);
}

// ---------------- layer-2 aggregation + fused log_softmax -------------------
__global__ __launch_bounds__(128) void agg2_k(
    const float* __restrict__ xl, const float* __restrict__ xr,
    const int* __restrict__ csr, const int* __restrict__ off,
    const float* __restrict__ att, const float* __restrict__ bias,
    float* __restrict__ out, int n)
{
    int w = (blockIdx.x * blockDim.x + threadIdx.x) >> 5;
    if (w >= n) return;
    int lane = threadIdx.x & 31;
    bool lo = (lane < 16);
    float a0 = att[lane];
    float a1 = lo ? att[32 + lane] : 0.f;
    float xr0 = xr[(size_t)w * OUTC + lane];
    float xr1 = lo ? xr[(size_t)w * OUTC + 32 + lane] : 0.f;

    float m = -3e38f, l = 0.f, acc0 = 0.f, acc1 = 0.f;
    int k0 = off[w], k1 = off[w + 1];
    for (int k = k0; k < k1; k++) {
        int s = csr[k];
        float x0 = xl[(size_t)s * OUTC + lane];
        float x1 = lo ? xl[(size_t)s * OUTC + 32 + lane] : 0.f;
        float p = leaky(x0 + xr0) * a0 + leaky(x1 + xr1) * a1;
        #pragma unroll
        for (int o = 16; o; o >>= 1) p += __shfl_xor_sync(0xffffffffu, p, o);
        float mn = fmaxf(m, p);
        float sc = __expf(m - mn);
        float pe = __expf(p - mn);
        l = l * sc + pe;
        acc0 = acc0 * sc + pe * x0;
        acc1 = acc1 * sc + pe * x1;
        m = mn;
    }
    float inv = 1.f / (l + 1e-16f);
    float v0 = acc0 * inv + bias[lane];
    float v1 = lo ? (acc1 * inv + bias[32 + lane]) : -3e38f;

    float mx = fmaxf(v0, v1);
    #pragma unroll
    for (int o = 16; o; o >>= 1) mx = fmaxf(mx, __shfl_xor_sync(0xffffffffu, mx, o));
    float se = __expf(v0 - mx) + (lo ? __expf(v1 - mx) : 0.f);
    #pragma unroll
    for (int o = 16; o; o >>= 1) se += __shfl_xor_sync(0xffffffffu, se, o);
    float lse = logf(se) + mx;
    out[(size_t)w * OUTC + lane] = v0 - lse;
    if (lo) out[(size_t)w * OUTC + 32 + lane] = v1 - lse;
}

// ---------------- host orchestration ----------------------------------------
extern "C" void kernel_launch(void* const* d_in, const int* in_sizes, int n_in,
                              void* d_out, int out_size)
{
    const float* x     = (const float*)d_in[0];
    const float* Wl1   = (const float*)d_in[1];
    const float* bl1   = (const float*)d_in[2];
    const float* Wr1   = (const float*)d_in[3];
    const float* br1   = (const float*)d_in[4];
    const float* att1  = (const float*)d_in[5];
    const float* bias1 = (const float*)d_in[6];
    const float* Wl2   = (const float*)d_in[7];
    const float* bl2   = (const float*)d_in[8];
    const float* Wr2   = (const float*)d_in[9];
    const float* br2   = (const float*)d_in[10];
    const float* att2  = (const float*)d_in[11];
    const float* bias2 = (const float*)d_in[12];
    const int* src1    = (const int*)d_in[13];
    const int* dst1    = (const int*)d_in[14];
    const int* src2    = (const int*)d_in[15];
    const int* dst2    = (const int*)d_in[16];
    float* out = (float*)d_out;

    float *xl2, *xr2;
    __half *xl1h, *xr1h, *hh, *w1l, *w1r, *w2l, *w2r;
    int *deg1, *off1, *cur1, *csr1, *deg2, *off2, *cur2, *csr2, *bsums, *flags;
    cudaGetSymbolAddress((void**)&xl1h, g_xl1h);
    cudaGetSymbolAddress((void**)&xr1h, g_xr1h);
    cudaGetSymbolAddress((void**)&xl2, g_xl2);
    cudaGetSymbolAddress((void**)&xr2, g_xr2);
    cudaGetSymbolAddress((void**)&hh,  g_hh);
    cudaGetSymbolAddress((void**)&w1l, g_w1l);
    cudaGetSymbolAddress((void**)&w1r, g_w1r);
    cudaGetSymbolAddress((void**)&w2l, g_w2l);
    cudaGetSymbolAddress((void**)&w2r, g_w2r);
    cudaGetSymbolAddress((void**)&deg1, g_deg1);
    cudaGetSymbolAddress((void**)&off1, g_off1);
    cudaGetSymbolAddress((void**)&cur1, g_cur1);
    cudaGetSymbolAddress((void**)&csr1, g_csr1);
    cudaGetSymbolAddress((void**)&deg2, g_deg2);
    cudaGetSymbolAddress((void**)&off2, g_off2);
    cudaGetSymbolAddress((void**)&cur2, g_cur2);
    cudaGetSymbolAddress((void**)&csr2, g_csr2);
    cudaGetSymbolAddress((void**)&bsums, g_bsums);
    cudaGetSymbolAddress((void**)&flags, g_flags);

    const int SMEMF = 2 * 128 * ASTRIDE * (int)sizeof(__half);
    cudaFuncSetAttribute(gemm1_fused_k, cudaFuncAttributeMaxDynamicSharedMemorySize, SMEMF);

    // 1. prep: weight transposes + zero deg/flags (grid covers WTOT=90112!)
    const int prep_n = (WTOT > N1 + 1) ? WTOT : (N1 + 1);
    prep_k<<<(prep_n + 255) / 256, 256>>>(Wl1, Wr1, Wl2, Wr2, w1l, w1r, w2l, w2r,
                                          deg1, deg2, flags);

    // 2. layer-1 GEMM + hidden edge counting
    gemm1_fused_k<<<dim3(1, NGEMM1 + NCNT), 256, SMEMF>>>(
        x, w1l, w1r, bl1, br1, xl1h, xr1h, N1 / 128, dst1, dst2, deg1, deg2);

    // 3. one-launch scan (both layers) with lookback
    scan_lb_k<<<NB1 + NB2, 1024>>>(deg1, off1, cur1, deg2, off2, cur2, bsums, flags);

    // 4. scatter both layers (4 edges/thread)
    {
        const int ctot = E1 / 4 + E2 / 4;
        scatter_both_k<<<(ctot + 255) / 256, 256>>>(src1, dst1, cur1, csr1,
                                                    src2, dst2, cur2, csr2);
    }

    // 5. layer-1 aggregation
    agg1_k<<<N1, 64>>>(xl1h, xr1h, csr1, off1, att1, bias1, hh);

    // 6. merged layer-2 GEMMs
    hmma_gemm2_k<<<dim3(1, N1 / 128 + N2 / 128), 256>>>(hh, w2l, w2r, bl2, br2,
                                                        xl2, xr2, N1 / 128);

    // 7. layer-2 aggregation + log_softmax
    agg2_k<<<N2 / 4, 128>>>(xl2, xr2, csr2, off2, att2, bias2, out, N2);
}

// round 15
// speedup vs baseline: 1.0467x; 1.0467x over previous
#include <cuda_runtime.h>
#include <cuda_fp16.h>
#include <cstdint>

// Problem constants (fixed by the dataset)
#define N0 320000
#define N1 80000
#define N2 16000
#define E1 800000
#define E2 160000
#define INC 128
#define F1  256    // H1*HID = 4*64
#define OUTC 48

#define NGEMM1 (N0 / 128)          // 2500
#define NSCAT 235                  // ceil((E1/4 + E2/4) / 1024) scatter tail blocks
#define WTOT (2 * F1 * INC + 2 * OUTC * F1)   // 90112 weight-transpose elements
#define CAP 128                    // per-node bucket capacity (Poisson(10): P(deg>=128) ~ 1e-25 over all nodes)

// ---------------- scratch (static device globals; no runtime allocation) ----
__device__ __half g_xl1h[(size_t)N0 * F1];
__device__ __half g_xr1h[(size_t)N1 * F1];
__device__ __half g_hh [(size_t)N1 * F1];
__device__ __half g_w1l[(size_t)F1 * INC];
__device__ __half g_w1r[(size_t)F1 * INC];
__device__ __half g_w2l[(size_t)OUTC * F1];
__device__ __half g_w2r[(size_t)OUTC * F1];
__device__ float  g_xl2[(size_t)N1 * OUTC];
__device__ float  g_xr2[(size_t)N2 * OUTC];

__device__ int g_cnt1[N1];
__device__ int g_csr1[(size_t)N1 * CAP];   // 41 MB bucketed adjacency
__device__ int g_cnt2[N2];
__device__ int g_csr2[(size_t)N2 * CAP];   // 8 MB

// ---------------- helpers ----------------------------------------------------
__device__ __forceinline__ uint32_t smem_to_u32(const void* p) {
    uint32_t a;
    asm("{ .reg .u64 t; cvta.to.shared.u64 t, %1; cvt.u32.u64 %0, t; }" : "=r"(a) : "l"(p));
    return a;
}
__device__ __forceinline__ void ldm_x4(uint32_t* r, uint32_t addr) {
    asm volatile("ldmatrix.sync.aligned.m8n8.x4.shared.b16 {%0,%1,%2,%3}, [%4];"
                 : "=r"(r[0]), "=r"(r[1]), "=r"(r[2]), "=r"(r[3]) : "r"(addr));
}
__device__ __forceinline__ void ldm_x2(uint32_t* r, uint32_t addr) {
    asm volatile("ldmatrix.sync.aligned.m8n8.x2.shared.b16 {%0,%1}, [%2];"
                 : "=r"(r[0]), "=r"(r[1]) : "r"(addr));
}
__device__ __forceinline__ void mma16816(float* c, const uint32_t* a, const uint32_t* b) {
    asm volatile("mma.sync.aligned.m16n8k16.row.col.f32.f16.f16.f32 "
                 "{%0,%1,%2,%3}, {%4,%5,%6,%7}, {%8,%9}, {%0,%1,%2,%3};"
                 : "+f"(c[0]), "+f"(c[1]), "+f"(c[2]), "+f"(c[3])
                 : "r"(a[0]), "r"(a[1]), "r"(a[2]), "r"(a[3]), "r"(b[0]), "r"(b[1]));
}

// ---------------- prep: weight transposes + zero counters (one launch) ------
// Grid covers WTOT=90112 >= N1 (R12 lesson: grid must cover the transpose work).
__global__ void prep_k(const float* __restrict__ Wl1, const float* __restrict__ Wr1,
                       const float* __restrict__ Wl2, const float* __restrict__ Wr2,
                       __half* __restrict__ w1l, __half* __restrict__ w1r,
                       __half* __restrict__ w2l, __half* __restrict__ w2r,
                       int* __restrict__ cnt1, int* __restrict__ cnt2) {
    const int S1 = F1 * INC;     // 32768
    const int S2 = OUTC * F1;    // 12288
    int i = blockIdx.x * blockDim.x + threadIdx.x;
    if (i < S1) {
        int n = i / INC, k = i % INC;
        w1l[i] = __float2half(Wl1[(size_t)k * F1 + n]);
    } else if (i < 2 * S1) {
        int j = i - S1, n = j / INC, k = j % INC;
        w1r[j] = __float2half(Wr1[(size_t)k * F1 + n]);
    } else if (i < 2 * S1 + S2) {
        int j = i - 2 * S1, n = j / F1, k = j % F1;
        w2l[j] = __float2half(Wl2[(size_t)k * OUTC + n]);
    } else if (i < 2 * S1 + 2 * S2) {
        int j = i - 2 * S1 - S2, n = j / F1, k = j % F1;
        w2r[j] = __float2half(Wr2[(size_t)k * OUTC + n]);
    }
    if (i < N1) cnt1[i] = 0;
    if (i < N2) cnt2[i] = 0;
}

// ---------------- fused layer-1 GEMM + direct bucket scatter (one launch) ---
// blocks [0, NGEMM1): GEMM over 128 rows of x.
// blocks [NGEMM1, +NSCAT): scatter both edge lists into bucketed CSR (no scan).
#define ASTRIDE 136
__global__ __launch_bounds__(256) void gemm1_fused_k(
    const float* __restrict__ x,
    const __half* __restrict__ w1l, const __half* __restrict__ w1r,
    const float* __restrict__ bl1, const float* __restrict__ br1,
    __half* __restrict__ xl, __half* __restrict__ xr, int nr_blocks,
    const int* __restrict__ src1, const int* __restrict__ dst1,
    const int* __restrict__ src2, const int* __restrict__ dst2,
    int* __restrict__ cnt1, int* __restrict__ csr1,
    int* __restrict__ cnt2, int* __restrict__ csr2)
{
    int tid = threadIdx.x;
    if (blockIdx.y >= NGEMM1) {
        // -------- scatter role: 4 int4 per thread, direct bucket placement ----
        int cb = blockIdx.y - NGEMM1;
        #pragma unroll
        for (int u = 0; u < 4; u++) {
            int i = cb * 1024 + u * 256 + tid;
            if (i < E1 / 4) {
                int4 d = ((const int4*)dst1)[i];
                int4 sv = ((const int4*)src1)[i];
                csr1[(size_t)d.x * CAP + atomicAdd(&cnt1[d.x], 1)] = sv.x;
                csr1[(size_t)d.y * CAP + atomicAdd(&cnt1[d.y], 1)] = sv.y;
                csr1[(size_t)d.z * CAP + atomicAdd(&cnt1[d.z], 1)] = sv.z;
                csr1[(size_t)d.w * CAP + atomicAdd(&cnt1[d.w], 1)] = sv.w;
            } else if (i < E1 / 4 + E2 / 4) {
                int j = i - E1 / 4;
                int4 d = ((const int4*)dst2)[j];
                int4 sv = ((const int4*)src2)[j];
                csr2[(size_t)d.x * CAP + atomicAdd(&cnt2[d.x], 1)] = sv.x;
                csr2[(size_t)d.y * CAP + atomicAdd(&cnt2[d.y], 1)] = sv.y;
                csr2[(size_t)d.z * CAP + atomicAdd(&cnt2[d.z], 1)] = sv.z;
                csr2[(size_t)d.w * CAP + atomicAdd(&cnt2[d.w], 1)] = sv.w;
            }
        }
        return;
    }

    extern __shared__ __half sm[];
    __half* As = sm;
    __half* Bs = sm + 128 * ASTRIDE;

    int lane = tid & 31, wid = tid >> 5;
    int wm = wid >> 1, wn = wid & 1;
    size_t m0 = (size_t)blockIdx.y * 128;

    uint32_t asb = smem_to_u32(As), bsb = smem_to_u32(Bs);

    for (int i = tid; i < 2048; i += 256) {
        int r = i >> 4, c8 = (i & 15) * 8;
        const float* p = &x[(m0 + r) * INC + c8];
        float4 v0 = *(const float4*)p;
        float4 v1 = *(const float4*)(p + 4);
        __half2 h[4] = {__floats2half2_rn(v0.x, v0.y), __floats2half2_rn(v0.z, v0.w),
                        __floats2half2_rn(v1.x, v1.y), __floats2half2_rn(v1.z, v1.w)};
        *(uint4*)&As[r * ASTRIDE + c8] = *(uint4*)h;
    }

    int npass = (blockIdx.y < (unsigned)nr_blocks) ? 4 : 2;
    for (int pass = 0; pass < npass; pass++) {
        const __half* B = (pass < 2) ? w1l : w1r;
        const float* bias = (pass < 2) ? bl1 : br1;
        __half* dst = (pass < 2) ? xl : xr;
        int nb = (pass & 1) * 128;

        __syncthreads();
        for (int i = tid; i < 2048; i += 256) {
            int r = i >> 4, c8 = (i & 15) * 8;
            *(uint4*)&Bs[r * ASTRIDE + c8] = *(const uint4*)&B[(size_t)(nb + r) * INC + c8];
        }
        __syncthreads();

        float c[2][8][4] = {};
        #pragma unroll
        for (int kk = 0; kk < 8; kk++) {
            uint32_t af[2][4], bf[8][2];
            #pragma unroll
            for (int mt = 0; mt < 2; mt++) {
                int row = wm * 32 + mt * 16 + (lane & 7) + ((lane >> 3) & 1) * 8;
                int col = kk * 16 + (lane >> 4) * 8;
                ldm_x4(af[mt], asb + (uint32_t)(row * ASTRIDE + col) * 2);
            }
            #pragma unroll
            for (int nt = 0; nt < 8; nt++) {
                int row = wn * 64 + nt * 8 + (lane & 7);
                int col = kk * 16 + ((lane >> 3) & 1) * 8;
                ldm_x2(bf[nt], bsb + (uint32_t)(row * ASTRIDE + col) * 2);
            }
            #pragma unroll
            for (int mt = 0; mt < 2; mt++)
                #pragma unroll
                for (int nt = 0; nt < 8; nt++)
                    mma16816(c[mt][nt], af[mt], bf[nt]);
        }

        #pragma unroll
        for (int mt = 0; mt < 2; mt++) {
            size_t r0 = m0 + wm * 32 + mt * 16 + (lane >> 2);
            #pragma unroll
            for (int nt = 0; nt < 8; nt++) {
                int col = nb + wn * 64 + nt * 8 + (lane & 3) * 2;
                float bx = bias[col], by = bias[col + 1];
                *(__half2*)&dst[r0 * F1 + col] =
                    __floats2half2_rn(c[mt][nt][0] + bx, c[mt][nt][1] + by);
                *(__half2*)&dst[(r0 + 8) * F1 + col] =
                    __floats2half2_rn(c[mt][nt][2] + bx, c[mt][nt][3] + by);
            }
        }
    }
}

// ---------------- merged layer-2 GEMM ----------------------------------------
__global__ __launch_bounds__(256) void hmma_gemm2_k(
    const __half* __restrict__ A,
    const __half* __restrict__ BtL, const __half* __restrict__ BtR,
    const float* __restrict__ biasL, const float* __restrict__ biasR,
    float* __restrict__ CL, float* __restrict__ CR, int split)
{
    constexpr int BN = 48, WN = 24, NT = 3, K_DIM = F1, N_OUT = OUTC;
    __shared__ __half As[128][40];
    __shared__ __half Bs[BN][40];

    int tid = threadIdx.x, lane = tid & 31, wid = tid >> 5;
    int wm = wid >> 1, wn = wid & 1;

    const __half* Bt; const float* bias; float* C; size_t m0;
    if ((int)blockIdx.y < split) { Bt = BtL; bias = biasL; C = CL; m0 = (size_t)blockIdx.y * 128; }
    else                          { Bt = BtR; bias = biasR; C = CR; m0 = (size_t)(blockIdx.y - split) * 128; }

    uint32_t asb = smem_to_u32(As), bsb = smem_to_u32(Bs);
    float c[2][NT][4] = {};

    for (int k0 = 0; k0 < K_DIM; k0 += 32) {
        #pragma unroll
        for (int i = tid; i < 512; i += 256) {
            int r = i >> 2, cv = i & 3;
            *(uint4*)&As[r][cv * 8] = *(const uint4*)&A[(m0 + r) * K_DIM + k0 + cv * 8];
        }
        #pragma unroll
        for (int i = tid; i < BN * 4; i += 256) {
            int r = i >> 2, cv = i & 3;
            *(uint4*)&Bs[r][cv * 8] = *(const uint4*)&Bt[(size_t)r * K_DIM + k0 + cv * 8];
        }
        __syncthreads();

        #pragma unroll
        for (int kk = 0; kk < 2; kk++) {
            uint32_t af[2][4], bf[NT][2];
            #pragma unroll
            for (int mt = 0; mt < 2; mt++) {
                int row = wm * 32 + mt * 16 + (lane & 7) + ((lane >> 3) & 1) * 8;
                int col = kk * 16 + (lane >> 4) * 8;
                ldm_x4(af[mt], asb + (uint32_t)(row * 40 + col) * 2);
            }
            #pragma unroll
            for (int nt = 0; nt < NT; nt++) {
                int row = wn * WN + nt * 8 + (lane & 7);
                int col = kk * 16 + ((lane >> 3) & 1) * 8;
                ldm_x2(bf[nt], bsb + (uint32_t)(row * 40 + col) * 2);
            }
            #pragma unroll
            for (int mt = 0; mt < 2; mt++)
                #pragma unroll
                for (int nt = 0; nt < NT; nt++)
                    mma16816(c[mt][nt], af[mt], bf[nt]);
        }
        __syncthreads();
    }

    #pragma unroll
    for (int mt = 0; mt < 2; mt++) {
        size_t r0 = m0 + wm * 32 + mt * 16 + (lane >> 2);
        #pragma unroll
        for (int nt = 0; nt < NT; nt++) {
            int col = wn * WN + nt * 8 + (lane & 3) * 2;
            float bx = bias[col], by = bias[col + 1];
            float2 o0 = {c[mt][nt][0] + bx, c[mt][nt][1] + by};
            float2 o1 = {c[mt][nt][2] + bx, c[mt][nt][3] + by};
            *(float2*)&C[r0 * N_OUT + col] = o0;
            *(float2*)&C[(r0 + 8) * N_OUT + col] = o1;
        }
    }
}

__device__ __forceinline__ float leaky(float v) { return v > 0.f ? v : 0.2f * v; }

__device__ __forceinline__ float4 ldrow_h4(const __half* p) {
    uint2 u = *(const uint2*)p;
    __half2 h01 = *(__half2*)&u.x;
    __half2 h23 = *(__half2*)&u.y;
    float2 f01 = __half22float2(h01);
    float2 f23 = __half22float2(h23);
    return make_float4(f01.x, f01.y, f23.x, f23.y);
}

// ---------------- layer-1 aggregation (bucketed CSR) -------------------------
__global__ __launch_bounds__(64) void agg1_k(
    const __half* __restrict__ xl, const __half* __restrict__ xr,
    const int* __restrict__ csr, const int* __restrict__ cnt,
    const float* __restrict__ att, const float* __restrict__ bias,
    __half* __restrict__ out)
{
    int d = blockIdx.x;
    int t = threadIdx.x;
    int base = t * 4;
    float4 attv = *(const float4*)(att + base);
    float4 xrv  = ldrow_h4(xr + (size_t)d * F1 + base);

    float m = -3e38f, l = 0.f;
    float4 acc = {0.f, 0.f, 0.f, 0.f};

    const int* adj = csr + (size_t)d * CAP;
    int k1 = cnt[d];
    int k = 0;
    for (; k + 4 <= k1; k += 4) {
        int s0 = adj[k], s1 = adj[k + 1], s2 = adj[k + 2], s3 = adj[k + 3];
        float4 xa = ldrow_h4(xl + (size_t)s0 * F1 + base);
        float4 xb = ldrow_h4(xl + (size_t)s1 * F1 + base);
        float4 xc = ldrow_h4(xl + (size_t)s2 * F1 + base);
        float4 xd = ldrow_h4(xl + (size_t)s3 * F1 + base);
        float pa = leaky(xa.x + xrv.x) * attv.x + leaky(xa.y + xrv.y) * attv.y
                 + leaky(xa.z + xrv.z) * attv.z + leaky(xa.w + xrv.w) * attv.w;
        float pb = leaky(xb.x + xrv.x) * attv.x + leaky(xb.y + xrv.y) * attv.y
                 + leaky(xb.z + xrv.z) * attv.z + leaky(xb.w + xrv.w) * attv.w;
        float pc = leaky(xc.x + xrv.x) * attv.x + leaky(xc.y + xrv.y) * attv.y
                 + leaky(xc.z + xrv.z) * attv.z + leaky(xc.w + xrv.w) * attv.w;
        float pd = leaky(xd.x + xrv.x) * attv.x + leaky(xd.y + xrv.y) * attv.y
                 + leaky(xd.z + xrv.z) * attv.z + leaky(xd.w + xrv.w) * attv.w;
        #pragma unroll
        for (int o = 8; o; o >>= 1) {
            pa += __shfl_xor_sync(0xffffffffu, pa, o);
            pb += __shfl_xor_sync(0xffffffffu, pb, o);
            pc += __shfl_xor_sync(0xffffffffu, pc, o);
            pd += __shfl_xor_sync(0xffffffffu, pd, o);
        }
        float mn = fmaxf(fmaxf(m, fmaxf(pa, pb)), fmaxf(pc, pd));
        float sc = __expf(m - mn);
        float ea = __expf(pa - mn);
        float eb = __expf(pb - mn);
        float ec = __expf(pc - mn);
        float ed = __expf(pd - mn);
        l = l * sc + ea + eb + ec + ed;
        acc.x = acc.x * sc + ea * xa.x + eb * xb.x + ec * xc.x + ed * xd.x;
        acc.y = acc.y * sc + ea * xa.y + eb * xb.y + ec * xc.y + ed * xd.y;
        acc.z = acc.z * sc + ea * xa.z + eb * xb.z + ec * xc.z + ed * xd.z;
        acc.w = acc.w * sc + ea * xa.w + eb * xb.w + ec * xc.w + ed * xd.w;
        m = mn;
    }
    for (; k < k1; k++) {
        int s = adj[k];
        float4 xv = ldrow_h4(xl + (size_t)s * F1 + base);
        float p = leaky(xv.x + xrv.x) * attv.x + leaky(xv.y + xrv.y) * attv.y
                + leaky(xv.z + xrv.z) * attv.z + leaky(xv.w + xrv.w) * attv.w;
        #pragma unroll
        for (int o = 8; o; o >>= 1) p += __shfl_xor_sync(0xffffffffu, p, o);
        float mn = fmaxf(m, p);
        float sc = __expf(m - mn);
        float pe = __expf(p - mn);
        l = l * sc + pe;
        acc.x = acc.x * sc + pe * xv.x;
        acc.y = acc.y * sc + pe * xv.y;
        acc.z = acc.z * sc + pe * xv.z;
        acc.w = acc.w * sc + pe * xv.w;
        m = mn;
    }
    float inv = 1.f / (l + 1e-16f);
    float4 bv = *(const float4*)(bias + base);
    float ox = fmaxf(acc.x * inv + bv.x, 0.f);
    float oy = fmaxf(acc.y * inv + bv.y, 0.f);
    float oz = fmaxf(acc.z * inv + bv.z, 0.f);
    float ow = fmaxf(acc.w * inv + bv.w, 0.f);
    __half2* hp = (__half2*)(out + (size_t)d * F1 + base);
    hp[0] = __floats2half2_rn(ox, oy);
    hp[1] = __floats2half2_rn(oz, ow);
}

// ---------------- layer-2 aggregation + fused log_softmax (bucketed CSR) ----
__global__ __launch_bounds__(128) void agg2_k(
    const float* __restrict__ xl, const float* __restrict__ xr,
    const int* __restrict__ csr, const int* __restrict__ cnt,
    const float* __restrict__ att, const float* __restrict__ bias,
    float* __restrict__ out, int n)
{
    int w = (blockIdx.x * blockDim.x + threadIdx.x) >> 5;
    if (w >= n) return;
    int lane = threadIdx.x & 31;
    bool lo = (lane < 16);
    float a0 = att[lane];
    float a1 = lo ? att[32 + lane] : 0.f;
    float xr0 = xr[(size_t)w * OUTC + lane];
    float xr1 = lo ? xr[(size_t)w * OUTC + 32 + lane] : 0.f;

    float m = -3e38f, l = 0.f, acc0 = 0.f, acc1 = 0.f;
    const int* adj = csr + (size_t)w * CAP;
    int k1 = cnt[w];
    for (int k = 0; k < k1; k++) {
        int s = adj[k];
        float x0 = xl[(size_t)s * OUTC + lane];
        float x1 = lo ? xl[(size_t)s * OUTC + 32 + lane] : 0.f;
        float p = leaky(x0 + xr0) * a0 + leaky(x1 + xr1) * a1;
        #pragma unroll
        for (int o = 16; o; o >>= 1) p += __shfl_xor_sync(0xffffffffu, p, o);
        float mn = fmaxf(m, p);
        float sc = __expf(m - mn);
        float pe = __expf(p - mn);
        l = l * sc + pe;
        acc0 = acc0 * sc + pe * x0;
        acc1 = acc1 * sc + pe * x1;
        m = mn;
    }
    float inv = 1.f / (l + 1e-16f);
    float v0 = acc0 * inv + bias[lane];
    float v1 = lo ? (acc1 * inv + bias[32 + lane]) : -3e38f;

    float mx = fmaxf(v0, v1);
    #pragma unroll
    for (int o = 16; o; o >>= 1) mx = fmaxf(mx, __shfl_xor_sync(0xffffffffu, mx, o));
    float se = __expf(v0 - mx) + (lo ? __expf(v1 - mx) : 0.f);
    #pragma unroll
    for (int o = 16; o; o >>= 1) se += __shfl_xor_sync(0xffffffffu, se, o);
    float lse = logf(se) + mx;
    out[(size_t)w * OUTC + lane] = v0 - lse;
    if (lo) out[(size_t)w * OUTC + 32 + lane] = v1 - lse;
}

// ---------------- host orchestration ----------------------------------------
extern "C" void kernel_launch(void* const* d_in, const int* in_sizes, int n_in,
                              void* d_out, int out_size)
{
    const float* x     = (const float*)d_in[0];
    const float* Wl1   = (const float*)d_in[1];
    const float* bl1   = (const float*)d_in[2];
    const float* Wr1   = (const float*)d_in[3];
    const float* br1   = (const float*)d_in[4];
    const float* att1  = (const float*)d_in[5];
    const float* bias1 = (const float*)d_in[6];
    const float* Wl2   = (const float*)d_in[7];
    const float* bl2   = (const float*)d_in[8];
    const float* Wr2   = (const float*)d_in[9];
    const float* br2   = (const float*)d_in[10];
    const float* att2  = (const float*)d_in[11];
    const float* bias2 = (const float*)d_in[12];
    const int* src1    = (const int*)d_in[13];
    const int* dst1    = (const int*)d_in[14];
    const int* src2    = (const int*)d_in[15];
    const int* dst2    = (const int*)d_in[16];
    float* out = (float*)d_out;

    float *xl2, *xr2;
    __half *xl1h, *xr1h, *hh, *w1l, *w1r, *w2l, *w2r;
    int *cnt1, *csr1, *cnt2, *csr2;
    cudaGetSymbolAddress((void**)&xl1h, g_xl1h);
    cudaGetSymbolAddress((void**)&xr1h, g_xr1h);
    cudaGetSymbolAddress((void**)&xl2, g_xl2);
    cudaGetSymbolAddress((void**)&xr2, g_xr2);
    cudaGetSymbolAddress((void**)&hh,  g_hh);
    cudaGetSymbolAddress((void**)&w1l, g_w1l);
    cudaGetSymbolAddress((void**)&w1r, g_w1r);
    cudaGetSymbolAddress((void**)&w2l, g_w2l);
    cudaGetSymbolAddress((void**)&w2r, g_w2r);
    cudaGetSymbolAddress((void**)&cnt1, g_cnt1);
    cudaGetSymbolAddress((void**)&csr1, g_csr1);
    cudaGetSymbolAddress((void**)&cnt2, g_cnt2);
    cudaGetSymbolAddress((void**)&csr2, g_csr2);

    const int SMEMF = 2 * 128 * ASTRIDE * (int)sizeof(__half);
    cudaFuncSetAttribute(gemm1_fused_k, cudaFuncAttributeMaxDynamicSharedMemorySize, SMEMF);

    // 1. prep: weight transposes + zero bucket counters (grid covers WTOT)
    prep_k<<<(WTOT + 255) / 256, 256>>>(Wl1, Wr1, Wl2, Wr2, w1l, w1r, w2l, w2r,
                                        cnt1, cnt2);

    // 2. layer-1 GEMM + hidden bucket scatter for BOTH edge lists
    gemm1_fused_k<<<dim3(1, NGEMM1 + NSCAT), 256, SMEMF>>>(
        x, w1l, w1r, bl1, br1, xl1h, xr1h, N1 / 128,
        src1, dst1, src2, dst2, cnt1, csr1, cnt2, csr2);

    // 3. layer-1 aggregation
    agg1_k<<<N1, 64>>>(xl1h, xr1h, csr1, cnt1, att1, bias1, hh);

    // 4. merged layer-2 GEMMs
    hmma_gemm2_k<<<dim3(1, N1 / 128 + N2 / 128), 256>>>(hh, w2l, w2r, bl2, br2,
                                                        xl2, xr2, N1 / 128);

    // 5. layer-2 aggregation + log_softmax
    agg2_k<<<N2 / 4, 128>>>(xl2, xr2, csr2, cnt2, att2, bias2, out, N2);
}